// round 10
// baseline (speedup 1.0000x reference)
#include <cuda_runtime.h>
#include <cuda_bf16.h>
#include <math.h>

// Problem constants
#define B_   4
#define L_   4096
#define D_   1024
#define H_   16
#define M_   (B_ * L_)          // 16384
#define K2   2048               // stored split: [hi | lo]
#define EPS_ 1e-5f

// GEMM tile config: 128x128 CTA tile, 8 warps of 32x64, merged 3-term loop
#define BM 128
#define BN 128
#define KC 32                   // k per stage (64-byte rows, SW64)
#define NST 32                  // 1024 / KC stages
// stage = {Ah, Al, Bh, Bl} each 128 rows x 64 B = 8 KB -> 32 KB
#define ST_BYTES 32768
#define DSMEM_BYTES (3 * ST_BYTES + 1024)   // 99328, same as R7 (2 CTAs/SM)

// ---------------------------------------------------------------------------
// Scratch (device globals)
// ---------------------------------------------------------------------------
__device__ __align__(128) __nv_bfloat16 g_Qs [(size_t)M_ * K2];
__device__ __align__(128) __nv_bfloat16 g_VNs[(size_t)M_ * K2];
__device__ __align__(128) __nv_bfloat16 g_Wq [(size_t)D_ * K2];
__device__ __align__(128) __nv_bfloat16 g_Wk [(size_t)D_ * K2];
__device__ __align__(128) __nv_bfloat16 g_Wv [(size_t)D_ * K2];
__device__ __align__(128) __nv_bfloat16 g_Wo [(size_t)D_ * K2];
__device__ __align__(128) float g_phiq[(size_t)M_ * D_];
__device__ __align__(128) float g_phik[(size_t)M_ * D_];
__device__ __align__(128) float g_v   [(size_t)M_ * D_];
__device__ __align__(128) float g_KVp [64 * 8 * 64 * 64];   // per-chunk partials
__device__ __align__(128) float g_Ksp [64 * 8 * 64];

// ---------------------------------------------------------------------------
// Helpers
// ---------------------------------------------------------------------------
__device__ __forceinline__ unsigned smem_u32(const void* p) {
    unsigned a;
    asm("{ .reg .u64 t; cvta.to.shared.u64 t, %1; cvt.u32.u64 %0, t; }"
        : "=r"(a) : "l"(p));
    return a;
}
// Swizzle for 64-byte rows (Swizzle<2,4,3>): bits[5:4] ^= bits[8:7]
#define SWZ64(o) ((o) ^ ((((unsigned)(o)) >> 3) & 0x30))

#define CP_ASYNC16(dst, src) \
    asm volatile("cp.async.cg.shared.global [%0], [%1], 16;" :: "r"(dst), "l"(src))
#define CP_COMMIT() asm volatile("cp.async.commit_group;" ::: "memory")
#define CP_WAIT1()  asm volatile("cp.async.wait_group 1;" ::: "memory")
#define CP_WAIT0()  asm volatile("cp.async.wait_group 0;" ::: "memory")

#define LDSM4(r, a) \
    asm volatile("ldmatrix.sync.aligned.m8n8.x4.shared.b16 {%0,%1,%2,%3}, [%4];" \
                 : "=r"((r)[0]), "=r"((r)[1]), "=r"((r)[2]), "=r"((r)[3]) : "r"(a))

#define MMA16816(c, a, b0, b1) \
    asm volatile("mma.sync.aligned.m16n8k16.row.col.f32.bf16.bf16.f32 " \
                 "{%0,%1,%2,%3}, {%4,%5,%6,%7}, {%8,%9}, {%0,%1,%2,%3};" \
                 : "+f"((c)[0]), "+f"((c)[1]), "+f"((c)[2]), "+f"((c)[3]) \
                 : "r"((a)[0]), "r"((a)[1]), "r"((a)[2]), "r"((a)[3]),   \
                   "r"(b0), "r"(b1))

// ---------------------------------------------------------------------------
// Stage loader: {Ah, Al, Bh, Bl} for KC=32 columns; 8 cp.async per thread
// ---------------------------------------------------------------------------
__device__ __forceinline__ void load_stage(
    const __nv_bfloat16* __restrict__ A, const __nv_bfloat16* __restrict__ W,
    unsigned sb, int kb, int row0, int col0, int t)
{
    const int r = t >> 2, s = t & 3;        // r: 0..63, s: 16B segment
    const unsigned soff = s * 16;
#pragma unroll
    for (int i = 0; i < 2; i++) {
        const int rr = r + i * 64;
        const unsigned d = SWZ64(rr * 64 + soff);
        CP_ASYNC16(sb +         d, A + (size_t)(row0 + rr) * K2 + kb + s * 8);
        CP_ASYNC16(sb +  8192 + d, A + (size_t)(row0 + rr) * K2 + kb + 1024 + s * 8);
        CP_ASYNC16(sb + 16384 + d, W + (size_t)(col0 + rr) * K2 + kb + s * 8);
        CP_ASYNC16(sb + 24576 + d, W + (size_t)(col0 + rr) * K2 + kb + 1024 + s * 8);
    }
}

// ---------------------------------------------------------------------------
// GEMM: C = Ah·Bh + Al·Bh + Ah·Bl (+bias, optional phi)
// 256 threads = 8 warps (4 m x 2 n); warp computes 32x64. 32-stage, 3-ring.
// ---------------------------------------------------------------------------
__device__ __forceinline__ void tc_gemm_body(
    const __nv_bfloat16* __restrict__ A, const __nv_bfloat16* __restrict__ W,
    const float* __restrict__ bias, float* __restrict__ C, int act)
{
    extern __shared__ char dsm_raw[];
    unsigned draw = smem_u32(dsm_raw);
    unsigned sbase = (draw + 1023u) & ~1023u;

    const int t = threadIdx.x;
    const int wid = t >> 5, lane = t & 31;
    const int warp_m = wid & 3, warp_n = wid >> 2;
    const int row0 = blockIdx.y * BM;
    const int col0 = blockIdx.x * BN;

    float acc[2][8][4];
#pragma unroll
    for (int i = 0; i < 2; i++)
#pragma unroll
        for (int j = 0; j < 8; j++)
#pragma unroll
            for (int q = 0; q < 4; q++) acc[i][j][q] = 0.f;

    const int a_row = lane & 15, a_hi = (lane >> 4) * 16;
    const int b_g = lane >> 3;
    const int b_row = ((b_g >> 1) * 8) + (lane & 7);
    const int b_kb = (b_g & 1) * 16;

    load_stage(A, W, sbase,            0,  row0, col0, t); CP_COMMIT();
    load_stage(A, W, sbase + ST_BYTES, 32, row0, col0, t); CP_COMMIT();

    int stage = 0;
    for (int c = 0; c < NST; c++) {
        if (c == NST - 1) { CP_WAIT0(); } else { CP_WAIT1(); }
        __syncthreads();
        if (c + 2 < NST) {
            int ns = stage + 2; if (ns >= 3) ns -= 3;
            load_stage(A, W, sbase + ns * ST_BYTES, (c + 2) * KC, row0, col0, t);
            CP_COMMIT();
        }

        unsigned Ah = sbase + stage * ST_BYTES;
        unsigned Al = Ah + 8192;
        unsigned Bh = Ah + 16384;
        unsigned Bl = Ah + 24576;
#pragma unroll
        for (int ks = 0; ks < 2; ks++) {
            const unsigned a0off = SWZ64((warp_m * 32 + a_row) * 64 + ks * 32 + a_hi);
            const unsigned a1off = SWZ64((warp_m * 32 + 16 + a_row) * 64 + ks * 32 + a_hi);
            const unsigned b0off = SWZ64((warp_n * 64 + b_row) * 64 + ks * 32 + b_kb);
            const unsigned b1off = SWZ64((warp_n * 64 + 16 + b_row) * 64 + ks * 32 + b_kb);
            const unsigned b2off = SWZ64((warp_n * 64 + 32 + b_row) * 64 + ks * 32 + b_kb);
            const unsigned b3off = SWZ64((warp_n * 64 + 48 + b_row) * 64 + ks * 32 + b_kb);

            unsigned a[2][4], b[4][4];
            LDSM4(a[0], Ah + a0off);
            LDSM4(a[1], Ah + a1off);
            LDSM4(b[0], Bh + b0off);
            LDSM4(b[1], Bh + b1off);
            LDSM4(b[2], Bh + b2off);
            LDSM4(b[3], Bh + b3off);
            // Ah·Bh
#pragma unroll
            for (int mt = 0; mt < 2; mt++) {
                MMA16816(acc[mt][0], a[mt], b[0][0], b[0][1]);
                MMA16816(acc[mt][1], a[mt], b[0][2], b[0][3]);
                MMA16816(acc[mt][2], a[mt], b[1][0], b[1][1]);
                MMA16816(acc[mt][3], a[mt], b[1][2], b[1][3]);
                MMA16816(acc[mt][4], a[mt], b[2][0], b[2][1]);
                MMA16816(acc[mt][5], a[mt], b[2][2], b[2][3]);
                MMA16816(acc[mt][6], a[mt], b[3][0], b[3][1]);
                MMA16816(acc[mt][7], a[mt], b[3][2], b[3][3]);
            }
            // Al·Bh (reuse B fragments, overwrite A fragments)
            {
                unsigned al[2][4];
                LDSM4(al[0], Al + a0off);
                LDSM4(al[1], Al + a1off);
#pragma unroll
                for (int mt = 0; mt < 2; mt++) {
                    MMA16816(acc[mt][0], al[mt], b[0][0], b[0][1]);
                    MMA16816(acc[mt][1], al[mt], b[0][2], b[0][3]);
                    MMA16816(acc[mt][2], al[mt], b[1][0], b[1][1]);
                    MMA16816(acc[mt][3], al[mt], b[1][2], b[1][3]);
                    MMA16816(acc[mt][4], al[mt], b[2][0], b[2][1]);
                    MMA16816(acc[mt][5], al[mt], b[2][2], b[2][3]);
                    MMA16816(acc[mt][6], al[mt], b[3][0], b[3][1]);
                    MMA16816(acc[mt][7], al[mt], b[3][2], b[3][3]);
                }
            }
            // Ah·Bl (reuse A-hi fragments, overwrite B fragments)
            LDSM4(b[0], Bl + b0off);
            LDSM4(b[1], Bl + b1off);
            LDSM4(b[2], Bl + b2off);
            LDSM4(b[3], Bl + b3off);
#pragma unroll
            for (int mt = 0; mt < 2; mt++) {
                MMA16816(acc[mt][0], a[mt], b[0][0], b[0][1]);
                MMA16816(acc[mt][1], a[mt], b[0][2], b[0][3]);
                MMA16816(acc[mt][2], a[mt], b[1][0], b[1][1]);
                MMA16816(acc[mt][3], a[mt], b[1][2], b[1][3]);
                MMA16816(acc[mt][4], a[mt], b[2][0], b[2][1]);
                MMA16816(acc[mt][5], a[mt], b[2][2], b[2][3]);
                MMA16816(acc[mt][6], a[mt], b[3][0], b[3][1]);
                MMA16816(acc[mt][7], a[mt], b[3][2], b[3][3]);
            }
        }
        stage++; if (stage >= 3) stage = 0;
    }

    // Epilogue
#pragma unroll
    for (int mt = 0; mt < 2; mt++) {
        int row = row0 + warp_m * 32 + mt * 16 + (lane >> 2);
#pragma unroll
        for (int nt = 0; nt < 8; nt++) {
            int col = col0 + warp_n * 64 + nt * 8 + (lane & 3) * 2;
            float bv0 = bias[col], bv1 = bias[col + 1];
            float o0 = acc[mt][nt][0] + bv0;
            float o1 = acc[mt][nt][1] + bv1;
            float o2 = acc[mt][nt][2] + bv0;
            float o3 = acc[mt][nt][3] + bv1;
            if (act) {
                o0 = o0 > 0.f ? o0 + 1.f : __expf(o0);
                o1 = o1 > 0.f ? o1 + 1.f : __expf(o1);
                o2 = o2 > 0.f ? o2 + 1.f : __expf(o2);
                o3 = o3 > 0.f ? o3 + 1.f : __expf(o3);
            }
            *(float2*)(C + (size_t)row * D_ + col)       = make_float2(o0, o1);
            *(float2*)(C + (size_t)(row + 8) * D_ + col) = make_float2(o2, o3);
        }
    }
}

__global__ __launch_bounds__(256, 2) void qkv_tc(
    const float* __restrict__ bQ, const float* __restrict__ bK,
    const float* __restrict__ bV)
{
    const int z = blockIdx.z;
    const __nv_bfloat16* W = (z == 0) ? g_Wq : (z == 1) ? g_Wk : g_Wv;
    const float* bb        = (z == 0) ? bQ   : (z == 1) ? bK   : bV;
    float* C               = (z == 0) ? g_phiq : (z == 1) ? g_phik : g_v;
    tc_gemm_body(g_Qs, W, bb, C, z < 2);
}

__global__ __launch_bounds__(256, 2) void out_tc(
    const float* __restrict__ bO, float* __restrict__ out)
{
    tc_gemm_body(g_VNs, g_Wo, bO, out, 0);
}

// ---------------------------------------------------------------------------
// fp32 -> bf16 2-term split, stored [hi | lo] with K2 row stride
// ---------------------------------------------------------------------------
__device__ __forceinline__ void split_one(
    const float* __restrict__ in, __nv_bfloat16* __restrict__ out, size_t i)
{
    const float2 x = ((const float2*)in)[i];
    size_t r = i >> 9;
    int c2 = (int)(i & 511);
    __nv_bfloat16 h0 = __float2bfloat16(x.x), h1 = __float2bfloat16(x.y);
    __nv_bfloat16 l0 = __float2bfloat16(x.x - __bfloat162float(h0));
    __nv_bfloat16 l1 = __float2bfloat16(x.y - __bfloat162float(h1));
    unsigned hv = ((unsigned)__bfloat16_as_ushort(h1) << 16) | __bfloat16_as_ushort(h0);
    unsigned lv = ((unsigned)__bfloat16_as_ushort(l1) << 16) | __bfloat16_as_ushort(l0);
    unsigned* o = (unsigned*)(out + r * K2) + c2;
    o[0] = hv; o[512] = lv;
}

__global__ __launch_bounds__(256) void split_q_kernel(const float* __restrict__ Q)
{
    split_one(Q, g_Qs, (size_t)blockIdx.x * 256 + threadIdx.x);
}

__global__ __launch_bounds__(256) void split_w_kernel(
    const float* __restrict__ WQ, const float* __restrict__ WK,
    const float* __restrict__ WV, const float* __restrict__ WO)
{
    const int z = blockIdx.y;
    const float* in = (z == 0) ? WQ : (z == 1) ? WK : (z == 2) ? WV : WO;
    __nv_bfloat16* out = (z == 0) ? g_Wq : (z == 1) ? g_Wk : (z == 2) ? g_Wv : g_Wo;
    split_one(in, out, (size_t)blockIdx.x * 256 + threadIdx.x);
}

// ---------------------------------------------------------------------------
// KV partial accumulation: block (bh, y) writes its own partial (no atomics)
// ---------------------------------------------------------------------------
__global__ __launch_bounds__(256) void kv_kernel()
{
    const int bh = blockIdx.x;
    const int b = bh >> 4, h = bh & 15;
    const int l0 = blockIdx.y * 512;

    __shared__ float ks[16][64];
    __shared__ float vs[16][64];

    const int t = threadIdx.x;
    const int td = t >> 4, tmm = t & 15;
    const int lr = t >> 4, lc = (t & 15) * 4;

    float acc[4][4];
    float ksum[4] = {0.f, 0.f, 0.f, 0.f};
#pragma unroll
    for (int i = 0; i < 4; i++)
#pragma unroll
        for (int j = 0; j < 4; j++) acc[i][j] = 0.f;

    for (int lt = 0; lt < 512; lt += 16) {
        size_t base = ((size_t)(b * L_ + l0 + lt + lr)) * D_ + h * 64 + lc;
        float4 kq = *(const float4*)(g_phik + base);
        float4 vq = *(const float4*)(g_v + base);
        __syncthreads();
        *(float4*)&ks[lr][lc] = kq;
        *(float4*)&vs[lr][lc] = vq;
        __syncthreads();
#pragma unroll
        for (int ll = 0; ll < 16; ll++) {
            float ka[4], va[4];
#pragma unroll
            for (int i = 0; i < 4; i++) ka[i] = ks[ll][td * 4 + i];
#pragma unroll
            for (int j = 0; j < 4; j++) va[j] = vs[ll][tmm * 4 + j];
#pragma unroll
            for (int i = 0; i < 4; i++)
#pragma unroll
                for (int j = 0; j < 4; j++) acc[i][j] += ka[i] * va[j];
            if (tmm == 0) {
#pragma unroll
                for (int i = 0; i < 4; i++) ksum[i] += ka[i];
            }
        }
    }

    float* kvout = g_KVp + ((size_t)bh * 8 + blockIdx.y) * 4096;
#pragma unroll
    for (int i = 0; i < 4; i++)
#pragma unroll
        for (int j = 0; j < 4; j++)
            kvout[(td * 4 + i) * 64 + tmm * 4 + j] = acc[i][j];
    if (tmm == 0) {
#pragma unroll
        for (int i = 0; i < 4; i++)
            g_Ksp[((size_t)bh * 8 + blockIdx.y) * 64 + td * 4 + i] = ksum[i];
    }
}

// ---------------------------------------------------------------------------
// V_new: sums KV partials, warp handles 4 rows/pass, vectorized d-loop.
// Writes bf16 split [hi|lo] into g_VNs (K2 stride).
// ---------------------------------------------------------------------------
__global__ __launch_bounds__(256) void vnew_kernel()
{
    const int bh = blockIdx.x;
    const int b = bh >> 4, h = bh & 15;
    const int l0 = blockIdx.y * 512;

    __shared__ float KVs[64][64];
    __shared__ float Ks[64];
    __shared__ float pqs[8][4][64];

    const int t = threadIdx.x, w = t >> 5, lane = t & 31;

    for (int i = t; i < 1024; i += 256) {
        float4 s = make_float4(0.f, 0.f, 0.f, 0.f);
#pragma unroll
        for (int p = 0; p < 8; p++) {
            float4 v = ((const float4*)(g_KVp + ((size_t)bh * 8 + p) * 4096))[i];
            s.x += v.x; s.y += v.y; s.z += v.z; s.w += v.w;
        }
        ((float4*)KVs)[i] = s;
    }
    if (t < 64) {
        float s = 0.f;
#pragma unroll
        for (int p = 0; p < 8; p++) s += g_Ksp[((size_t)bh * 8 + p) * 64 + t];
        Ks[t] = s;
    }
    __syncthreads();

    const int prow = lane >> 3;          // 0..3
    const int pcol = (lane & 7) * 8;     // 0..56

    for (int s = 0; s < 16; s++) {
        const int lb = l0 + s * 32 + w * 4;
        const float* pq = g_phiq + ((size_t)(b * L_ + lb + prow)) * D_ + h * 64 + pcol;
        float4 pa = *(const float4*)pq;
        float4 pb = *(const float4*)(pq + 4);
        *(float4*)&pqs[w][prow][pcol]     = pa;
        *(float4*)&pqs[w][prow][pcol + 4] = pb;

        float zp = pa.x * Ks[pcol]     + pa.y * Ks[pcol + 1]
                 + pa.z * Ks[pcol + 2] + pa.w * Ks[pcol + 3]
                 + pb.x * Ks[pcol + 4] + pb.y * Ks[pcol + 5]
                 + pb.z * Ks[pcol + 6] + pb.w * Ks[pcol + 7];
        zp += __shfl_xor_sync(0xffffffffu, zp, 1);
        zp += __shfl_xor_sync(0xffffffffu, zp, 2);
        zp += __shfl_xor_sync(0xffffffffu, zp, 4);
        float z0 = 1.f / (__shfl_sync(0xffffffffu, zp, 0)  + EPS_);
        float z1 = 1.f / (__shfl_sync(0xffffffffu, zp, 8)  + EPS_);
        float z2 = 1.f / (__shfl_sync(0xffffffffu, zp, 16) + EPS_);
        float z3 = 1.f / (__shfl_sync(0xffffffffu, zp, 24) + EPS_);
        __syncwarp();

        float2 a0 = {0.f, 0.f}, a1 = {0.f, 0.f}, a2 = {0.f, 0.f}, a3 = {0.f, 0.f};
        const float4* q40 = (const float4*)&pqs[w][0][0];
        const float4* q41 = (const float4*)&pqs[w][1][0];
        const float4* q42 = (const float4*)&pqs[w][2][0];
        const float4* q43 = (const float4*)&pqs[w][3][0];
#pragma unroll
        for (int d4 = 0; d4 < 16; d4++) {
            float4 q0 = q40[d4], q1 = q41[d4], q2 = q42[d4], q3 = q43[d4];
            float2 kv0 = *(const float2*)&KVs[d4 * 4 + 0][lane * 2];
            float2 kv1 = *(const float2*)&KVs[d4 * 4 + 1][lane * 2];
            float2 kv2 = *(const float2*)&KVs[d4 * 4 + 2][lane * 2];
            float2 kv3 = *(const float2*)&KVs[d4 * 4 + 3][lane * 2];
            a0.x += q0.x * kv0.x + q0.y * kv1.x + q0.z * kv2.x + q0.w * kv3.x;
            a0.y += q0.x * kv0.y + q0.y * kv1.y + q0.z * kv2.y + q0.w * kv3.y;
            a1.x += q1.x * kv0.x + q1.y * kv1.x + q1.z * kv2.x + q1.w * kv3.x;
            a1.y += q1.x * kv0.y + q1.y * kv1.y + q1.z * kv2.y + q1.w * kv3.y;
            a2.x += q2.x * kv0.x + q2.y * kv1.x + q2.z * kv2.x + q2.w * kv3.x;
            a2.y += q2.x * kv0.y + q2.y * kv1.y + q2.z * kv2.y + q2.w * kv3.y;
            a3.x += q3.x * kv0.x + q3.y * kv1.x + q3.z * kv2.x + q3.w * kv3.x;
            a3.y += q3.x * kv0.y + q3.y * kv1.y + q3.z * kv2.y + q3.w * kv3.y;
        }

        float2 vv[4] = {
            {a0.x * z0, a0.y * z0}, {a1.x * z1, a1.y * z1},
            {a2.x * z2, a2.y * z2}, {a3.x * z3, a3.y * z3}
        };
#pragma unroll
        for (int j = 0; j < 4; j++) {
            __nv_bfloat16 h0 = __float2bfloat16(vv[j].x);
            __nv_bfloat16 h1 = __float2bfloat16(vv[j].y);
            __nv_bfloat16 q0 = __float2bfloat16(vv[j].x - __bfloat162float(h0));
            __nv_bfloat16 q1 = __float2bfloat16(vv[j].y - __bfloat162float(h1));
            unsigned hv = ((unsigned)__bfloat16_as_ushort(h1) << 16) | __bfloat16_as_ushort(h0);
            unsigned lv = ((unsigned)__bfloat16_as_ushort(q1) << 16) | __bfloat16_as_ushort(q0);
            unsigned* p = (unsigned*)(g_VNs + (size_t)(b * L_ + lb + j) * K2) + h * 32 + lane;
            p[0] = hv; p[512] = lv;
        }
        __syncwarp();
    }
}

// ---------------------------------------------------------------------------
// Launch
// ---------------------------------------------------------------------------
extern "C" void kernel_launch(void* const* d_in, const int* in_sizes, int n_in,
                              void* d_out, int out_size)
{
    const float* Q  = (const float*)d_in[0];
    const float* WQ = (const float*)d_in[1];
    const float* bQ = (const float*)d_in[2];
    const float* WK = (const float*)d_in[3];
    const float* bK = (const float*)d_in[4];
    const float* WV = (const float*)d_in[5];
    const float* bV = (const float*)d_in[6];
    const float* WO = (const float*)d_in[7];
    const float* bO = (const float*)d_in[8];
    float* out = (float*)d_out;

    cudaFuncSetAttribute(qkv_tc, cudaFuncAttributeMaxDynamicSharedMemorySize, DSMEM_BYTES);
    cudaFuncSetAttribute(out_tc, cudaFuncAttributeMaxDynamicSharedMemorySize, DSMEM_BYTES);

    split_q_kernel<<<(M_ * 512) / 256, 256>>>(Q);
    {
        dim3 grid((D_ * 512) / 256, 4);
        split_w_kernel<<<grid, 256>>>(WQ, WK, WV, WO);
    }

    {
        dim3 grid(D_ / BN, M_ / BM, 3);
        qkv_tc<<<grid, 256, DSMEM_BYTES>>>(bQ, bK, bV);
    }
    {
        dim3 grid(64, 8);
        kv_kernel<<<grid, 256>>>();
    }
    {
        dim3 grid(64, 8);
        vnew_kernel<<<grid, 256>>>();
    }
    {
        dim3 grid(D_ / BN, M_ / BM);
        out_tc<<<grid, 256, DSMEM_BYTES>>>(bO, out);
    }
}

// round 11
// speedup vs baseline: 1.3134x; 1.3134x over previous
#include <cuda_runtime.h>
#include <cuda_bf16.h>
#include <cuda_fp16.h>
#include <math.h>

// Problem constants
#define B_   4
#define L_   4096
#define D_   1024
#define H_   16
#define M_   (B_ * L_)          // 16384
#define K2   2048               // stored split: [hi | lo] (fp16)
#define EPS_ 1e-5f

// GEMM tile config: 128x128 CTA tile, 8 warps of 32x64, 2-term fp16
#define BM 128
#define BN 128
#define KC 32                   // k per stage (64-byte rows, SW64)
#define NST 32                  // 1024 / KC stages
// stage = {Ah, Al, Bh} each 128 rows x 64 B = 8 KB -> 24 KB
#define ST_BYTES 24576
#define DSMEM_BYTES (3 * ST_BYTES + 1024)

#define NPART 16                // kv partials per bh

// ---------------------------------------------------------------------------
// Scratch (device globals)
// ---------------------------------------------------------------------------
__device__ __align__(128) __half g_Qs [(size_t)M_ * K2];
__device__ __align__(128) __half g_VNs[(size_t)M_ * K2];
__device__ __align__(128) __half g_Wq [(size_t)D_ * K2];
__device__ __align__(128) __half g_Wk [(size_t)D_ * K2];
__device__ __align__(128) __half g_Wv [(size_t)D_ * K2];
__device__ __align__(128) __half g_Wo [(size_t)D_ * K2];
__device__ __align__(128) float g_phiq[(size_t)M_ * D_];
__device__ __align__(128) float g_phik[(size_t)M_ * D_];
__device__ __align__(128) float g_v   [(size_t)M_ * D_];
__device__ __align__(128) float g_KVp [64 * NPART * 64 * 64];
__device__ __align__(128) float g_Ksp [64 * NPART * 64];

// ---------------------------------------------------------------------------
// Helpers
// ---------------------------------------------------------------------------
__device__ __forceinline__ unsigned smem_u32(const void* p) {
    unsigned a;
    asm("{ .reg .u64 t; cvta.to.shared.u64 t, %1; cvt.u32.u64 %0, t; }"
        : "=r"(a) : "l"(p));
    return a;
}
// Swizzle for 64-byte rows (Swizzle<2,4,3>): bits[5:4] ^= bits[8:7]
#define SWZ64(o) ((o) ^ ((((unsigned)(o)) >> 3) & 0x30))

#define CP_ASYNC16(dst, src) \
    asm volatile("cp.async.cg.shared.global [%0], [%1], 16;" :: "r"(dst), "l"(src))
#define CP_COMMIT() asm volatile("cp.async.commit_group;" ::: "memory")
#define CP_WAIT1()  asm volatile("cp.async.wait_group 1;" ::: "memory")
#define CP_WAIT0()  asm volatile("cp.async.wait_group 0;" ::: "memory")

#define LDSM4(r, a) \
    asm volatile("ldmatrix.sync.aligned.m8n8.x4.shared.b16 {%0,%1,%2,%3}, [%4];" \
                 : "=r"((r)[0]), "=r"((r)[1]), "=r"((r)[2]), "=r"((r)[3]) : "r"(a))

#define MMA16816F(c, a, b0, b1) \
    asm volatile("mma.sync.aligned.m16n8k16.row.col.f32.f16.f16.f32 " \
                 "{%0,%1,%2,%3}, {%4,%5,%6,%7}, {%8,%9}, {%0,%1,%2,%3};" \
                 : "+f"((c)[0]), "+f"((c)[1]), "+f"((c)[2]), "+f"((c)[3]) \
                 : "r"((a)[0]), "r"((a)[1]), "r"((a)[2]), "r"((a)[3]),   \
                   "r"(b0), "r"(b1))

// ---------------------------------------------------------------------------
// Stage loader: {Ah, Al, Bh} for KC=32 columns; 6 cp.async per thread
// ---------------------------------------------------------------------------
__device__ __forceinline__ void load_stage(
    const __half* __restrict__ A, const __half* __restrict__ W,
    unsigned sb, int kb, int row0, int col0, int t)
{
    const int r = t >> 2, s = t & 3;        // r: 0..63, s: 16B segment
    const unsigned soff = s * 16;
#pragma unroll
    for (int i = 0; i < 2; i++) {
        const int rr = r + i * 64;
        const unsigned d = SWZ64(rr * 64 + soff);
        CP_ASYNC16(sb +         d, A + (size_t)(row0 + rr) * K2 + kb + s * 8);
        CP_ASYNC16(sb +  8192 + d, A + (size_t)(row0 + rr) * K2 + kb + 1024 + s * 8);
        CP_ASYNC16(sb + 16384 + d, W + (size_t)(col0 + rr) * K2 + kb + s * 8);
    }
}

// ---------------------------------------------------------------------------
// GEMM: C = Ah·Bh + Al·Bh (+bias, optional phi). fp16 2-term split.
// 256 threads = 8 warps (4 m x 2 n); warp computes 32x64. 32-stage, 3-ring.
// ---------------------------------------------------------------------------
__device__ __forceinline__ void tc_gemm_body(
    const __half* __restrict__ A, const __half* __restrict__ W,
    const float* __restrict__ bias, float* __restrict__ C, int act)
{
    extern __shared__ char dsm_raw[];
    unsigned draw = smem_u32(dsm_raw);
    unsigned sbase = (draw + 1023u) & ~1023u;

    const int t = threadIdx.x;
    const int wid = t >> 5, lane = t & 31;
    const int warp_m = wid & 3, warp_n = wid >> 2;
    const int row0 = blockIdx.y * BM;
    const int col0 = blockIdx.x * BN;

    float acc[2][8][4];
#pragma unroll
    for (int i = 0; i < 2; i++)
#pragma unroll
        for (int j = 0; j < 8; j++)
#pragma unroll
            for (int q = 0; q < 4; q++) acc[i][j][q] = 0.f;

    const int a_row = lane & 15, a_hi = (lane >> 4) * 16;
    const int b_g = lane >> 3;
    const int b_row = ((b_g >> 1) * 8) + (lane & 7);
    const int b_kb = (b_g & 1) * 16;

    load_stage(A, W, sbase,            0,  row0, col0, t); CP_COMMIT();
    load_stage(A, W, sbase + ST_BYTES, 32, row0, col0, t); CP_COMMIT();

    int stage = 0;
    for (int c = 0; c < NST; c++) {
        if (c == NST - 1) { CP_WAIT0(); } else { CP_WAIT1(); }
        __syncthreads();
        if (c + 2 < NST) {
            int ns = stage + 2; if (ns >= 3) ns -= 3;
            load_stage(A, W, sbase + ns * ST_BYTES, (c + 2) * KC, row0, col0, t);
            CP_COMMIT();
        }

        unsigned Ah = sbase + stage * ST_BYTES;
        unsigned Al = Ah + 8192;
        unsigned Bh = Ah + 16384;
#pragma unroll
        for (int ks = 0; ks < 2; ks++) {
            const unsigned a0off = SWZ64((warp_m * 32 + a_row) * 64 + ks * 32 + a_hi);
            const unsigned a1off = SWZ64((warp_m * 32 + 16 + a_row) * 64 + ks * 32 + a_hi);
            const unsigned b0off = SWZ64((warp_n * 64 + b_row) * 64 + ks * 32 + b_kb);
            const unsigned b1off = SWZ64((warp_n * 64 + 16 + b_row) * 64 + ks * 32 + b_kb);
            const unsigned b2off = SWZ64((warp_n * 64 + 32 + b_row) * 64 + ks * 32 + b_kb);
            const unsigned b3off = SWZ64((warp_n * 64 + 48 + b_row) * 64 + ks * 32 + b_kb);

            unsigned a[2][4], b[4][4];
            LDSM4(a[0], Ah + a0off);
            LDSM4(a[1], Ah + a1off);
            LDSM4(b[0], Bh + b0off);
            LDSM4(b[1], Bh + b1off);
            LDSM4(b[2], Bh + b2off);
            LDSM4(b[3], Bh + b3off);
            // Ah·Bh
#pragma unroll
            for (int mt = 0; mt < 2; mt++) {
                MMA16816F(acc[mt][0], a[mt], b[0][0], b[0][1]);
                MMA16816F(acc[mt][1], a[mt], b[0][2], b[0][3]);
                MMA16816F(acc[mt][2], a[mt], b[1][0], b[1][1]);
                MMA16816F(acc[mt][3], a[mt], b[1][2], b[1][3]);
                MMA16816F(acc[mt][4], a[mt], b[2][0], b[2][1]);
                MMA16816F(acc[mt][5], a[mt], b[2][2], b[2][3]);
                MMA16816F(acc[mt][6], a[mt], b[3][0], b[3][1]);
                MMA16816F(acc[mt][7], a[mt], b[3][2], b[3][3]);
            }
            // Al·Bh (reuse B fragments)
            {
                unsigned al[2][4];
                LDSM4(al[0], Al + a0off);
                LDSM4(al[1], Al + a1off);
#pragma unroll
                for (int mt = 0; mt < 2; mt++) {
                    MMA16816F(acc[mt][0], al[mt], b[0][0], b[0][1]);
                    MMA16816F(acc[mt][1], al[mt], b[0][2], b[0][3]);
                    MMA16816F(acc[mt][2], al[mt], b[1][0], b[1][1]);
                    MMA16816F(acc[mt][3], al[mt], b[1][2], b[1][3]);
                    MMA16816F(acc[mt][4], al[mt], b[2][0], b[2][1]);
                    MMA16816F(acc[mt][5], al[mt], b[2][2], b[2][3]);
                    MMA16816F(acc[mt][6], al[mt], b[3][0], b[3][1]);
                    MMA16816F(acc[mt][7], al[mt], b[3][2], b[3][3]);
                }
            }
        }
        stage++; if (stage >= 3) stage = 0;
    }

    // Epilogue
#pragma unroll
    for (int mt = 0; mt < 2; mt++) {
        int row = row0 + warp_m * 32 + mt * 16 + (lane >> 2);
#pragma unroll
        for (int nt = 0; nt < 8; nt++) {
            int col = col0 + warp_n * 64 + nt * 8 + (lane & 3) * 2;
            float bv0 = bias[col], bv1 = bias[col + 1];
            float o0 = acc[mt][nt][0] + bv0;
            float o1 = acc[mt][nt][1] + bv1;
            float o2 = acc[mt][nt][2] + bv0;
            float o3 = acc[mt][nt][3] + bv1;
            if (act) {
                o0 = o0 > 0.f ? o0 + 1.f : __expf(o0);
                o1 = o1 > 0.f ? o1 + 1.f : __expf(o1);
                o2 = o2 > 0.f ? o2 + 1.f : __expf(o2);
                o3 = o3 > 0.f ? o3 + 1.f : __expf(o3);
            }
            *(float2*)(C + (size_t)row * D_ + col)       = make_float2(o0, o1);
            *(float2*)(C + (size_t)(row + 8) * D_ + col) = make_float2(o2, o3);
        }
    }
}

__global__ __launch_bounds__(256, 2) void qkv_tc(
    const float* __restrict__ bQ, const float* __restrict__ bK,
    const float* __restrict__ bV)
{
    const int z = blockIdx.z;
    const __half* W  = (z == 0) ? g_Wq : (z == 1) ? g_Wk : g_Wv;
    const float* bb  = (z == 0) ? bQ   : (z == 1) ? bK   : bV;
    float* C         = (z == 0) ? g_phiq : (z == 1) ? g_phik : g_v;
    tc_gemm_body(g_Qs, W, bb, C, z < 2);
}

__global__ __launch_bounds__(256, 2) void out_tc(
    const float* __restrict__ bO, float* __restrict__ out)
{
    tc_gemm_body(g_VNs, g_Wo, bO, out, 0);
}

// ---------------------------------------------------------------------------
// fp32 -> fp16 2-term split, stored [hi | lo] with K2 row stride
// ---------------------------------------------------------------------------
__device__ __forceinline__ void split_one(
    const float* __restrict__ in, __half* __restrict__ out, size_t i)
{
    const float2 x = ((const float2*)in)[i];
    size_t r = i >> 9;
    int c2 = (int)(i & 511);
    __half h0 = __float2half_rn(x.x), h1 = __float2half_rn(x.y);
    __half l0 = __float2half_rn(x.x - __half2float(h0));
    __half l1 = __float2half_rn(x.y - __half2float(h1));
    unsigned hv = ((unsigned)__half_as_ushort(h1) << 16) | __half_as_ushort(h0);
    unsigned lv = ((unsigned)__half_as_ushort(l1) << 16) | __half_as_ushort(l0);
    unsigned* o = (unsigned*)(out + r * K2) + c2;
    o[0] = hv; o[512] = lv;
}

__global__ __launch_bounds__(256) void split_q_kernel(const float* __restrict__ Q)
{
    split_one(Q, g_Qs, (size_t)blockIdx.x * 256 + threadIdx.x);
}

__global__ __launch_bounds__(256) void split_w_kernel(
    const float* __restrict__ WQ, const float* __restrict__ WK,
    const float* __restrict__ WV, const float* __restrict__ WO)
{
    const int z = blockIdx.y;
    const float* in = (z == 0) ? WQ : (z == 1) ? WK : (z == 2) ? WV : WO;
    __half* out = (z == 0) ? g_Wq : (z == 1) ? g_Wk : (z == 2) ? g_Wv : g_Wo;
    split_one(in, out, (size_t)blockIdx.x * 256 + threadIdx.x);
}

// ---------------------------------------------------------------------------
// KV partial accumulation: block (bh, y) handles 256 l-rows (no atomics)
// ---------------------------------------------------------------------------
__global__ __launch_bounds__(256) void kv_kernel()
{
    const int bh = blockIdx.x;
    const int b = bh >> 4, h = bh & 15;
    const int l0 = blockIdx.y * 256;

    __shared__ float ks[16][64];
    __shared__ float vs[16][64];

    const int t = threadIdx.x;
    const int td = t >> 4, tmm = t & 15;
    const int lr = t >> 4, lc = (t & 15) * 4;

    float acc[4][4];
    float ksum[4] = {0.f, 0.f, 0.f, 0.f};
#pragma unroll
    for (int i = 0; i < 4; i++)
#pragma unroll
        for (int j = 0; j < 4; j++) acc[i][j] = 0.f;

    for (int lt = 0; lt < 256; lt += 16) {
        size_t base = ((size_t)(b * L_ + l0 + lt + lr)) * D_ + h * 64 + lc;
        float4 kq = *(const float4*)(g_phik + base);
        float4 vq = *(const float4*)(g_v + base);
        __syncthreads();
        *(float4*)&ks[lr][lc] = kq;
        *(float4*)&vs[lr][lc] = vq;
        __syncthreads();
#pragma unroll
        for (int ll = 0; ll < 16; ll++) {
            float ka[4], va[4];
#pragma unroll
            for (int i = 0; i < 4; i++) ka[i] = ks[ll][td * 4 + i];
#pragma unroll
            for (int j = 0; j < 4; j++) va[j] = vs[ll][tmm * 4 + j];
#pragma unroll
            for (int i = 0; i < 4; i++)
#pragma unroll
                for (int j = 0; j < 4; j++) acc[i][j] += ka[i] * va[j];
            if (tmm == 0) {
#pragma unroll
                for (int i = 0; i < 4; i++) ksum[i] += ka[i];
            }
        }
    }

    float* kvout = g_KVp + ((size_t)bh * NPART + blockIdx.y) * 4096;
#pragma unroll
    for (int i = 0; i < 4; i++)
#pragma unroll
        for (int j = 0; j < 4; j++)
            kvout[(td * 4 + i) * 64 + tmm * 4 + j] = acc[i][j];
    if (tmm == 0) {
#pragma unroll
        for (int i = 0; i < 4; i++)
            g_Ksp[((size_t)bh * NPART + blockIdx.y) * 64 + td * 4 + i] = ksum[i];
    }
}

// ---------------------------------------------------------------------------
// V_new: sums KV partials, warp handles 4 rows/pass, vectorized d-loop.
// Writes fp16 split [hi|lo] into g_VNs (K2 stride). Block covers 256 l-rows.
// ---------------------------------------------------------------------------
__global__ __launch_bounds__(256) void vnew_kernel()
{
    const int bh = blockIdx.x;
    const int b = bh >> 4, h = bh & 15;
    const int l0 = blockIdx.y * 256;

    __shared__ float KVs[64][64];
    __shared__ float Ks[64];
    __shared__ float pqs[8][4][64];

    const int t = threadIdx.x, w = t >> 5, lane = t & 31;

    for (int i = t; i < 1024; i += 256) {
        float4 s = make_float4(0.f, 0.f, 0.f, 0.f);
#pragma unroll
        for (int p = 0; p < NPART; p++) {
            float4 v = ((const float4*)(g_KVp + ((size_t)bh * NPART + p) * 4096))[i];
            s.x += v.x; s.y += v.y; s.z += v.z; s.w += v.w;
        }
        ((float4*)KVs)[i] = s;
    }
    if (t < 64) {
        float s = 0.f;
#pragma unroll
        for (int p = 0; p < NPART; p++) s += g_Ksp[((size_t)bh * NPART + p) * 64 + t];
        Ks[t] = s;
    }
    __syncthreads();

    const int prow = lane >> 3;          // 0..3
    const int pcol = (lane & 7) * 8;     // 0..56

    for (int s = 0; s < 8; s++) {
        const int lb = l0 + s * 32 + w * 4;
        const float* pq = g_phiq + ((size_t)(b * L_ + lb + prow)) * D_ + h * 64 + pcol;
        float4 pa = *(const float4*)pq;
        float4 pb = *(const float4*)(pq + 4);
        *(float4*)&pqs[w][prow][pcol]     = pa;
        *(float4*)&pqs[w][prow][pcol + 4] = pb;

        float zp = pa.x * Ks[pcol]     + pa.y * Ks[pcol + 1]
                 + pa.z * Ks[pcol + 2] + pa.w * Ks[pcol + 3]
                 + pb.x * Ks[pcol + 4] + pb.y * Ks[pcol + 5]
                 + pb.z * Ks[pcol + 6] + pb.w * Ks[pcol + 7];
        zp += __shfl_xor_sync(0xffffffffu, zp, 1);
        zp += __shfl_xor_sync(0xffffffffu, zp, 2);
        zp += __shfl_xor_sync(0xffffffffu, zp, 4);
        float z0 = 1.f / (__shfl_sync(0xffffffffu, zp, 0)  + EPS_);
        float z1 = 1.f / (__shfl_sync(0xffffffffu, zp, 8)  + EPS_);
        float z2 = 1.f / (__shfl_sync(0xffffffffu, zp, 16) + EPS_);
        float z3 = 1.f / (__shfl_sync(0xffffffffu, zp, 24) + EPS_);
        __syncwarp();

        float2 a0 = {0.f, 0.f}, a1 = {0.f, 0.f}, a2 = {0.f, 0.f}, a3 = {0.f, 0.f};
        const float4* q40 = (const float4*)&pqs[w][0][0];
        const float4* q41 = (const float4*)&pqs[w][1][0];
        const float4* q42 = (const float4*)&pqs[w][2][0];
        const float4* q43 = (const float4*)&pqs[w][3][0];
#pragma unroll
        for (int d4 = 0; d4 < 16; d4++) {
            float4 q0 = q40[d4], q1 = q41[d4], q2 = q42[d4], q3 = q43[d4];
            float2 kv0 = *(const float2*)&KVs[d4 * 4 + 0][lane * 2];
            float2 kv1 = *(const float2*)&KVs[d4 * 4 + 1][lane * 2];
            float2 kv2 = *(const float2*)&KVs[d4 * 4 + 2][lane * 2];
            float2 kv3 = *(const float2*)&KVs[d4 * 4 + 3][lane * 2];
            a0.x += q0.x * kv0.x + q0.y * kv1.x + q0.z * kv2.x + q0.w * kv3.x;
            a0.y += q0.x * kv0.y + q0.y * kv1.y + q0.z * kv2.y + q0.w * kv3.y;
            a1.x += q1.x * kv0.x + q1.y * kv1.x + q1.z * kv2.x + q1.w * kv3.x;
            a1.y += q1.x * kv0.y + q1.y * kv1.y + q1.z * kv2.y + q1.w * kv3.y;
            a2.x += q2.x * kv0.x + q2.y * kv1.x + q2.z * kv2.x + q2.w * kv3.x;
            a2.y += q2.x * kv0.y + q2.y * kv1.y + q2.z * kv2.y + q2.w * kv3.y;
            a3.x += q3.x * kv0.x + q3.y * kv1.x + q3.z * kv2.x + q3.w * kv3.x;
            a3.y += q3.x * kv0.y + q3.y * kv1.y + q3.z * kv2.y + q3.w * kv3.y;
        }

        float2 vv[4] = {
            {a0.x * z0, a0.y * z0}, {a1.x * z1, a1.y * z1},
            {a2.x * z2, a2.y * z2}, {a3.x * z3, a3.y * z3}
        };
#pragma unroll
        for (int j = 0; j < 4; j++) {
            __half h0 = __float2half_rn(vv[j].x);
            __half h1 = __float2half_rn(vv[j].y);
            __half q0 = __float2half_rn(vv[j].x - __half2float(h0));
            __half q1 = __float2half_rn(vv[j].y - __half2float(h1));
            unsigned hv = ((unsigned)__half_as_ushort(h1) << 16) | __half_as_ushort(h0);
            unsigned lv = ((unsigned)__half_as_ushort(q1) << 16) | __half_as_ushort(q0);
            unsigned* p = (unsigned*)(g_VNs + (size_t)(b * L_ + lb + j) * K2) + h * 32 + lane;
            p[0] = hv; p[512] = lv;
        }
        __syncwarp();
    }
}

// ---------------------------------------------------------------------------
// Launch
// ---------------------------------------------------------------------------
extern "C" void kernel_launch(void* const* d_in, const int* in_sizes, int n_in,
                              void* d_out, int out_size)
{
    const float* Q  = (const float*)d_in[0];
    const float* WQ = (const float*)d_in[1];
    const float* bQ = (const float*)d_in[2];
    const float* WK = (const float*)d_in[3];
    const float* bK = (const float*)d_in[4];
    const float* WV = (const float*)d_in[5];
    const float* bV = (const float*)d_in[6];
    const float* WO = (const float*)d_in[7];
    const float* bO = (const float*)d_in[8];
    float* out = (float*)d_out;

    cudaFuncSetAttribute(qkv_tc, cudaFuncAttributeMaxDynamicSharedMemorySize, DSMEM_BYTES);
    cudaFuncSetAttribute(out_tc, cudaFuncAttributeMaxDynamicSharedMemorySize, DSMEM_BYTES);

    split_q_kernel<<<(M_ * 512) / 256, 256>>>(Q);
    {
        dim3 grid((D_ * 512) / 256, 4);
        split_w_kernel<<<grid, 256>>>(WQ, WK, WV, WO);
    }

    {
        dim3 grid(D_ / BN, M_ / BM, 3);
        qkv_tc<<<grid, 256, DSMEM_BYTES>>>(bQ, bK, bV);
    }
    {
        dim3 grid(64, NPART);
        kv_kernel<<<grid, 256>>>();
    }
    {
        dim3 grid(64, NPART);
        vnew_kernel<<<grid, 256>>>();
    }
    {
        dim3 grid(D_ / BN, M_ / BM);
        out_tc<<<grid, 256, DSMEM_BYTES>>>(bO, out);
    }
}

// round 12
// speedup vs baseline: 1.3178x; 1.0034x over previous
#include <cuda_runtime.h>
#include <cuda_bf16.h>
#include <cuda_fp16.h>
#include <math.h>

// Problem constants
#define B_   4
#define L_   4096
#define D_   1024
#define H_   16
#define M_   (B_ * L_)          // 16384
#define K2   2048               // stored split: [hi | lo] (fp16)
#define EPS_ 1e-5f

// GEMM tile config: 128x128 CTA tile, 8 warps of 32x64, 2-term fp16
#define BM 128
#define BN 128
#define KC 32                   // k per stage (64-byte rows, SW64)
#define NST 32                  // 1024 / KC stages
// stage = {Ah, Al, Bh} each 128 rows x 64 B = 8 KB -> 24 KB
#define ST_BYTES 24576
#define DSMEM_BYTES (3 * ST_BYTES + 1024)

#define NPART 16                // kv partials per bh

// ---------------------------------------------------------------------------
// Scratch (device globals)
// ---------------------------------------------------------------------------
__device__ __align__(128) __half g_Qs [(size_t)M_ * K2];
__device__ __align__(128) __half g_VNs[(size_t)M_ * K2];
__device__ __align__(128) __half g_Wq [(size_t)D_ * K2];
__device__ __align__(128) __half g_Wk [(size_t)D_ * K2];
__device__ __align__(128) __half g_Wv [(size_t)D_ * K2];
__device__ __align__(128) __half g_Wo [(size_t)D_ * K2];
__device__ __align__(128) float g_phiq[(size_t)M_ * D_];
__device__ __align__(128) float g_phik[(size_t)M_ * D_];
__device__ __align__(128) float g_v   [(size_t)M_ * D_];
__device__ __align__(128) float g_KVp [64 * NPART * 64 * 64];
__device__ __align__(128) float g_Ksp [64 * NPART * 64];

// ---------------------------------------------------------------------------
// Helpers
// ---------------------------------------------------------------------------
__device__ __forceinline__ unsigned smem_u32(const void* p) {
    unsigned a;
    asm("{ .reg .u64 t; cvta.to.shared.u64 t, %1; cvt.u32.u64 %0, t; }"
        : "=r"(a) : "l"(p));
    return a;
}
// Swizzle for 64-byte rows (Swizzle<2,4,3>): bits[5:4] ^= bits[8:7]
#define SWZ64(o) ((o) ^ ((((unsigned)(o)) >> 3) & 0x30))

#define CP_ASYNC16(dst, src) \
    asm volatile("cp.async.cg.shared.global [%0], [%1], 16;" :: "r"(dst), "l"(src))
#define CP_COMMIT() asm volatile("cp.async.commit_group;" ::: "memory")
#define CP_WAIT1()  asm volatile("cp.async.wait_group 1;" ::: "memory")
#define CP_WAIT0()  asm volatile("cp.async.wait_group 0;" ::: "memory")

#define LDSM4(r, a) \
    asm volatile("ldmatrix.sync.aligned.m8n8.x4.shared.b16 {%0,%1,%2,%3}, [%4];" \
                 : "=r"((r)[0]), "=r"((r)[1]), "=r"((r)[2]), "=r"((r)[3]) : "r"(a))

#define MMA16816F(c, a, b0, b1) \
    asm volatile("mma.sync.aligned.m16n8k16.row.col.f32.f16.f16.f32 " \
                 "{%0,%1,%2,%3}, {%4,%5,%6,%7}, {%8,%9}, {%0,%1,%2,%3};" \
                 : "+f"((c)[0]), "+f"((c)[1]), "+f"((c)[2]), "+f"((c)[3]) \
                 : "r"((a)[0]), "r"((a)[1]), "r"((a)[2]), "r"((a)[3]),   \
                   "r"(b0), "r"(b1))

// ---------------------------------------------------------------------------
// Stage loader: {Ah, Al, Bh} for KC=32 columns; 6 cp.async per thread
// ---------------------------------------------------------------------------
__device__ __forceinline__ void load_stage(
    const __half* __restrict__ A, const __half* __restrict__ W,
    unsigned sb, int kb, int row0, int col0, int t)
{
    const int r = t >> 2, s = t & 3;        // r: 0..63, s: 16B segment
    const unsigned soff = s * 16;
#pragma unroll
    for (int i = 0; i < 2; i++) {
        const int rr = r + i * 64;
        const unsigned d = SWZ64(rr * 64 + soff);
        CP_ASYNC16(sb +         d, A + (size_t)(row0 + rr) * K2 + kb + s * 8);
        CP_ASYNC16(sb +  8192 + d, A + (size_t)(row0 + rr) * K2 + kb + 1024 + s * 8);
        CP_ASYNC16(sb + 16384 + d, W + (size_t)(col0 + rr) * K2 + kb + s * 8);
    }
}

// ---------------------------------------------------------------------------
// GEMM: C = Ah·Bh + Al·Bh (+bias, optional phi). fp16 2-term split.
// 256 threads = 8 warps (4 m x 2 n); warp computes 32x64. 32-stage, 3-ring.
// ---------------------------------------------------------------------------
__device__ __forceinline__ void tc_gemm_body(
    const __half* __restrict__ A, const __half* __restrict__ W,
    const float* __restrict__ bias, float* __restrict__ C, int act)
{
    extern __shared__ char dsm_raw[];
    unsigned draw = smem_u32(dsm_raw);
    unsigned sbase = (draw + 1023u) & ~1023u;

    const int t = threadIdx.x;
    const int wid = t >> 5, lane = t & 31;
    const int warp_m = wid & 3, warp_n = wid >> 2;
    const int row0 = blockIdx.y * BM;
    const int col0 = blockIdx.x * BN;

    float acc[2][8][4];
#pragma unroll
    for (int i = 0; i < 2; i++)
#pragma unroll
        for (int j = 0; j < 8; j++)
#pragma unroll
            for (int q = 0; q < 4; q++) acc[i][j][q] = 0.f;

    const int a_row = lane & 15, a_hi = (lane >> 4) * 16;
    const int b_g = lane >> 3;
    const int b_row = ((b_g >> 1) * 8) + (lane & 7);
    const int b_kb = (b_g & 1) * 16;

    load_stage(A, W, sbase,            0,  row0, col0, t); CP_COMMIT();
    load_stage(A, W, sbase + ST_BYTES, 32, row0, col0, t); CP_COMMIT();

    int stage = 0;
    for (int c = 0; c < NST; c++) {
        if (c == NST - 1) { CP_WAIT0(); } else { CP_WAIT1(); }
        __syncthreads();
        if (c + 2 < NST) {
            int ns = stage + 2; if (ns >= 3) ns -= 3;
            load_stage(A, W, sbase + ns * ST_BYTES, (c + 2) * KC, row0, col0, t);
            CP_COMMIT();
        }

        unsigned Ah = sbase + stage * ST_BYTES;
        unsigned Al = Ah + 8192;
        unsigned Bh = Ah + 16384;
#pragma unroll
        for (int ks = 0; ks < 2; ks++) {
            const unsigned a0off = SWZ64((warp_m * 32 + a_row) * 64 + ks * 32 + a_hi);
            const unsigned a1off = SWZ64((warp_m * 32 + 16 + a_row) * 64 + ks * 32 + a_hi);
            const unsigned b0off = SWZ64((warp_n * 64 + b_row) * 64 + ks * 32 + b_kb);
            const unsigned b1off = SWZ64((warp_n * 64 + 16 + b_row) * 64 + ks * 32 + b_kb);
            const unsigned b2off = SWZ64((warp_n * 64 + 32 + b_row) * 64 + ks * 32 + b_kb);
            const unsigned b3off = SWZ64((warp_n * 64 + 48 + b_row) * 64 + ks * 32 + b_kb);

            unsigned a[2][4], b[4][4];
            LDSM4(a[0], Ah + a0off);
            LDSM4(a[1], Ah + a1off);
            LDSM4(b[0], Bh + b0off);
            LDSM4(b[1], Bh + b1off);
            LDSM4(b[2], Bh + b2off);
            LDSM4(b[3], Bh + b3off);
            // Ah·Bh
#pragma unroll
            for (int mt = 0; mt < 2; mt++) {
                MMA16816F(acc[mt][0], a[mt], b[0][0], b[0][1]);
                MMA16816F(acc[mt][1], a[mt], b[0][2], b[0][3]);
                MMA16816F(acc[mt][2], a[mt], b[1][0], b[1][1]);
                MMA16816F(acc[mt][3], a[mt], b[1][2], b[1][3]);
                MMA16816F(acc[mt][4], a[mt], b[2][0], b[2][1]);
                MMA16816F(acc[mt][5], a[mt], b[2][2], b[2][3]);
                MMA16816F(acc[mt][6], a[mt], b[3][0], b[3][1]);
                MMA16816F(acc[mt][7], a[mt], b[3][2], b[3][3]);
            }
            // Al·Bh (reuse B fragments)
            {
                unsigned al[2][4];
                LDSM4(al[0], Al + a0off);
                LDSM4(al[1], Al + a1off);
#pragma unroll
                for (int mt = 0; mt < 2; mt++) {
                    MMA16816F(acc[mt][0], al[mt], b[0][0], b[0][1]);
                    MMA16816F(acc[mt][1], al[mt], b[0][2], b[0][3]);
                    MMA16816F(acc[mt][2], al[mt], b[1][0], b[1][1]);
                    MMA16816F(acc[mt][3], al[mt], b[1][2], b[1][3]);
                    MMA16816F(acc[mt][4], al[mt], b[2][0], b[2][1]);
                    MMA16816F(acc[mt][5], al[mt], b[2][2], b[2][3]);
                    MMA16816F(acc[mt][6], al[mt], b[3][0], b[3][1]);
                    MMA16816F(acc[mt][7], al[mt], b[3][2], b[3][3]);
                }
            }
        }
        stage++; if (stage >= 3) stage = 0;
    }

    // Epilogue
#pragma unroll
    for (int mt = 0; mt < 2; mt++) {
        int row = row0 + warp_m * 32 + mt * 16 + (lane >> 2);
#pragma unroll
        for (int nt = 0; nt < 8; nt++) {
            int col = col0 + warp_n * 64 + nt * 8 + (lane & 3) * 2;
            float bv0 = bias[col], bv1 = bias[col + 1];
            float o0 = acc[mt][nt][0] + bv0;
            float o1 = acc[mt][nt][1] + bv1;
            float o2 = acc[mt][nt][2] + bv0;
            float o3 = acc[mt][nt][3] + bv1;
            if (act) {
                o0 = o0 > 0.f ? o0 + 1.f : __expf(o0);
                o1 = o1 > 0.f ? o1 + 1.f : __expf(o1);
                o2 = o2 > 0.f ? o2 + 1.f : __expf(o2);
                o3 = o3 > 0.f ? o3 + 1.f : __expf(o3);
            }
            *(float2*)(C + (size_t)row * D_ + col)       = make_float2(o0, o1);
            *(float2*)(C + (size_t)(row + 8) * D_ + col) = make_float2(o2, o3);
        }
    }
}

__global__ __launch_bounds__(256, 2) void qkv_tc(
    const float* __restrict__ bQ, const float* __restrict__ bK,
    const float* __restrict__ bV)
{
    const int z = blockIdx.z;
    const __half* W  = (z == 0) ? g_Wq : (z == 1) ? g_Wk : g_Wv;
    const float* bb  = (z == 0) ? bQ   : (z == 1) ? bK   : bV;
    float* C         = (z == 0) ? g_phiq : (z == 1) ? g_phik : g_v;
    tc_gemm_body(g_Qs, W, bb, C, z < 2);
}

__global__ __launch_bounds__(256, 2) void out_tc(
    const float* __restrict__ bO, float* __restrict__ out)
{
    tc_gemm_body(g_VNs, g_Wo, bO, out, 0);
}

// ---------------------------------------------------------------------------
// fp32 -> fp16 2-term split, stored [hi | lo] with K2 row stride
// ---------------------------------------------------------------------------
__device__ __forceinline__ void split_one(
    const float* __restrict__ in, __half* __restrict__ out, size_t i)
{
    const float2 x = ((const float2*)in)[i];
    size_t r = i >> 9;
    int c2 = (int)(i & 511);
    __half h0 = __float2half_rn(x.x), h1 = __float2half_rn(x.y);
    __half l0 = __float2half_rn(x.x - __half2float(h0));
    __half l1 = __float2half_rn(x.y - __half2float(h1));
    unsigned hv = ((unsigned)__half_as_ushort(h1) << 16) | __half_as_ushort(h0);
    unsigned lv = ((unsigned)__half_as_ushort(l1) << 16) | __half_as_ushort(l0);
    unsigned* o = (unsigned*)(out + r * K2) + c2;
    o[0] = hv; o[512] = lv;
}

__global__ __launch_bounds__(256) void split_q_kernel(const float* __restrict__ Q)
{
    split_one(Q, g_Qs, (size_t)blockIdx.x * 256 + threadIdx.x);
}

__global__ __launch_bounds__(256) void split_w_kernel(
    const float* __restrict__ WQ, const float* __restrict__ WK,
    const float* __restrict__ WV, const float* __restrict__ WO)
{
    const int z = blockIdx.y;
    const float* in = (z == 0) ? WQ : (z == 1) ? WK : (z == 2) ? WV : WO;
    __half* out = (z == 0) ? g_Wq : (z == 1) ? g_Wk : (z == 2) ? g_Wv : g_Wo;
    split_one(in, out, (size_t)blockIdx.x * 256 + threadIdx.x);
}

// ---------------------------------------------------------------------------
// KV partial accumulation: block (bh, y) handles 256 l-rows (no atomics)
// ---------------------------------------------------------------------------
__global__ __launch_bounds__(256) void kv_kernel()
{
    const int bh = blockIdx.x;
    const int b = bh >> 4, h = bh & 15;
    const int l0 = blockIdx.y * 256;

    __shared__ float ks[16][64];
    __shared__ float vs[16][64];

    const int t = threadIdx.x;
    const int td = t >> 4, tmm = t & 15;
    const int lr = t >> 4, lc = (t & 15) * 4;

    float acc[4][4];
    float ksum[4] = {0.f, 0.f, 0.f, 0.f};
#pragma unroll
    for (int i = 0; i < 4; i++)
#pragma unroll
        for (int j = 0; j < 4; j++) acc[i][j] = 0.f;

    for (int lt = 0; lt < 256; lt += 16) {
        size_t base = ((size_t)(b * L_ + l0 + lt + lr)) * D_ + h * 64 + lc;
        float4 kq = *(const float4*)(g_phik + base);
        float4 vq = *(const float4*)(g_v + base);
        __syncthreads();
        *(float4*)&ks[lr][lc] = kq;
        *(float4*)&vs[lr][lc] = vq;
        __syncthreads();
#pragma unroll
        for (int ll = 0; ll < 16; ll++) {
            float ka[4], va[4];
#pragma unroll
            for (int i = 0; i < 4; i++) ka[i] = ks[ll][td * 4 + i];
#pragma unroll
            for (int j = 0; j < 4; j++) va[j] = vs[ll][tmm * 4 + j];
#pragma unroll
            for (int i = 0; i < 4; i++)
#pragma unroll
                for (int j = 0; j < 4; j++) acc[i][j] += ka[i] * va[j];
            if (tmm == 0) {
#pragma unroll
                for (int i = 0; i < 4; i++) ksum[i] += ka[i];
            }
        }
    }

    float* kvout = g_KVp + ((size_t)bh * NPART + blockIdx.y) * 4096;
#pragma unroll
    for (int i = 0; i < 4; i++)
#pragma unroll
        for (int j = 0; j < 4; j++)
            kvout[(td * 4 + i) * 64 + tmm * 4 + j] = acc[i][j];
    if (tmm == 0) {
#pragma unroll
        for (int i = 0; i < 4; i++)
            g_Ksp[((size_t)bh * NPART + blockIdx.y) * 64 + td * 4 + i] = ksum[i];
    }
}

// ---------------------------------------------------------------------------
// V_new: sums KV partials, warp handles 4 rows/pass, vectorized d-loop.
// Writes fp16 split [hi|lo] into g_VNs (K2 stride). Block covers 256 l-rows.
// ---------------------------------------------------------------------------
__global__ __launch_bounds__(256) void vnew_kernel()
{
    const int bh = blockIdx.x;
    const int b = bh >> 4, h = bh & 15;
    const int l0 = blockIdx.y * 256;

    __shared__ float KVs[64][64];
    __shared__ float Ks[64];
    __shared__ float pqs[8][4][64];

    const int t = threadIdx.x, w = t >> 5, lane = t & 31;

    for (int i = t; i < 1024; i += 256) {
        float4 s = make_float4(0.f, 0.f, 0.f, 0.f);
#pragma unroll
        for (int p = 0; p < NPART; p++) {
            float4 v = ((const float4*)(g_KVp + ((size_t)bh * NPART + p) * 4096))[i];
            s.x += v.x; s.y += v.y; s.z += v.z; s.w += v.w;
        }
        ((float4*)KVs)[i] = s;
    }
    if (t < 64) {
        float s = 0.f;
#pragma unroll
        for (int p = 0; p < NPART; p++) s += g_Ksp[((size_t)bh * NPART + p) * 64 + t];
        Ks[t] = s;
    }
    __syncthreads();

    const int prow = lane >> 3;          // 0..3
    const int pcol = (lane & 7) * 8;     // 0..56

    for (int s = 0; s < 8; s++) {
        const int lb = l0 + s * 32 + w * 4;
        const float* pq = g_phiq + ((size_t)(b * L_ + lb + prow)) * D_ + h * 64 + pcol;
        float4 pa = *(const float4*)pq;
        float4 pb = *(const float4*)(pq + 4);
        *(float4*)&pqs[w][prow][pcol]     = pa;
        *(float4*)&pqs[w][prow][pcol + 4] = pb;

        float zp = pa.x * Ks[pcol]     + pa.y * Ks[pcol + 1]
                 + pa.z * Ks[pcol + 2] + pa.w * Ks[pcol + 3]
                 + pb.x * Ks[pcol + 4] + pb.y * Ks[pcol + 5]
                 + pb.z * Ks[pcol + 6] + pb.w * Ks[pcol + 7];
        zp += __shfl_xor_sync(0xffffffffu, zp, 1);
        zp += __shfl_xor_sync(0xffffffffu, zp, 2);
        zp += __shfl_xor_sync(0xffffffffu, zp, 4);
        float z0 = 1.f / (__shfl_sync(0xffffffffu, zp, 0)  + EPS_);
        float z1 = 1.f / (__shfl_sync(0xffffffffu, zp, 8)  + EPS_);
        float z2 = 1.f / (__shfl_sync(0xffffffffu, zp, 16) + EPS_);
        float z3 = 1.f / (__shfl_sync(0xffffffffu, zp, 24) + EPS_);
        __syncwarp();

        float2 a0 = {0.f, 0.f}, a1 = {0.f, 0.f}, a2 = {0.f, 0.f}, a3 = {0.f, 0.f};
        const float4* q40 = (const float4*)&pqs[w][0][0];
        const float4* q41 = (const float4*)&pqs[w][1][0];
        const float4* q42 = (const float4*)&pqs[w][2][0];
        const float4* q43 = (const float4*)&pqs[w][3][0];
#pragma unroll
        for (int d4 = 0; d4 < 16; d4++) {
            float4 q0 = q40[d4], q1 = q41[d4], q2 = q42[d4], q3 = q43[d4];
            float2 kv0 = *(const float2*)&KVs[d4 * 4 + 0][lane * 2];
            float2 kv1 = *(const float2*)&KVs[d4 * 4 + 1][lane * 2];
            float2 kv2 = *(const float2*)&KVs[d4 * 4 + 2][lane * 2];
            float2 kv3 = *(const float2*)&KVs[d4 * 4 + 3][lane * 2];
            a0.x += q0.x * kv0.x + q0.y * kv1.x + q0.z * kv2.x + q0.w * kv3.x;
            a0.y += q0.x * kv0.y + q0.y * kv1.y + q0.z * kv2.y + q0.w * kv3.y;
            a1.x += q1.x * kv0.x + q1.y * kv1.x + q1.z * kv2.x + q1.w * kv3.x;
            a1.y += q1.x * kv0.y + q1.y * kv1.y + q1.z * kv2.y + q1.w * kv3.y;
            a2.x += q2.x * kv0.x + q2.y * kv1.x + q2.z * kv2.x + q2.w * kv3.x;
            a2.y += q2.x * kv0.y + q2.y * kv1.y + q2.z * kv2.y + q2.w * kv3.y;
            a3.x += q3.x * kv0.x + q3.y * kv1.x + q3.z * kv2.x + q3.w * kv3.x;
            a3.y += q3.x * kv0.y + q3.y * kv1.y + q3.z * kv2.y + q3.w * kv3.y;
        }

        float2 vv[4] = {
            {a0.x * z0, a0.y * z0}, {a1.x * z1, a1.y * z1},
            {a2.x * z2, a2.y * z2}, {a3.x * z3, a3.y * z3}
        };
#pragma unroll
        for (int j = 0; j < 4; j++) {
            __half h0 = __float2half_rn(vv[j].x);
            __half h1 = __float2half_rn(vv[j].y);
            __half q0 = __float2half_rn(vv[j].x - __half2float(h0));
            __half q1 = __float2half_rn(vv[j].y - __half2float(h1));
            unsigned hv = ((unsigned)__half_as_ushort(h1) << 16) | __half_as_ushort(h0);
            unsigned lv = ((unsigned)__half_as_ushort(q1) << 16) | __half_as_ushort(q0);
            unsigned* p = (unsigned*)(g_VNs + (size_t)(b * L_ + lb + j) * K2) + h * 32 + lane;
            p[0] = hv; p[512] = lv;
        }
        __syncwarp();
    }
}

// ---------------------------------------------------------------------------
// Launch
// ---------------------------------------------------------------------------
extern "C" void kernel_launch(void* const* d_in, const int* in_sizes, int n_in,
                              void* d_out, int out_size)
{
    const float* Q  = (const float*)d_in[0];
    const float* WQ = (const float*)d_in[1];
    const float* bQ = (const float*)d_in[2];
    const float* WK = (const float*)d_in[3];
    const float* bK = (const float*)d_in[4];
    const float* WV = (const float*)d_in[5];
    const float* bV = (const float*)d_in[6];
    const float* WO = (const float*)d_in[7];
    const float* bO = (const float*)d_in[8];
    float* out = (float*)d_out;

    cudaFuncSetAttribute(qkv_tc, cudaFuncAttributeMaxDynamicSharedMemorySize, DSMEM_BYTES);
    cudaFuncSetAttribute(out_tc, cudaFuncAttributeMaxDynamicSharedMemorySize, DSMEM_BYTES);

    split_q_kernel<<<(M_ * 512) / 256, 256>>>(Q);
    {
        dim3 grid((D_ * 512) / 256, 4);
        split_w_kernel<<<grid, 256>>>(WQ, WK, WV, WO);
    }

    {
        dim3 grid(D_ / BN, M_ / BM, 3);
        qkv_tc<<<grid, 256, DSMEM_BYTES>>>(bQ, bK, bV);
    }
    {
        dim3 grid(64, NPART);
        kv_kernel<<<grid, 256>>>();
    }
    {
        dim3 grid(64, NPART);
        vnew_kernel<<<grid, 256>>>();
    }
    {
        dim3 grid(D_ / BN, M_ / BM);
        out_tc<<<grid, 256, DSMEM_BYTES>>>(bO, out);
    }
}

// round 13
// speedup vs baseline: 1.3201x; 1.0017x over previous
#include <cuda_runtime.h>
#include <cuda_bf16.h>
#include <cuda_fp16.h>
#include <math.h>

// Problem constants
#define B_   4
#define L_   4096
#define D_   1024
#define H_   16
#define M_   (B_ * L_)          // 16384
#define K2   2048               // stored split: [hi | lo] (fp16)
#define EPS_ 1e-5f

// GEMM tile config: 128x128 CTA tile, 8 warps of 32x64, 2-term fp16
#define BM 128
#define BN 128
#define KC 32                   // k per stage (64-byte rows, SW64)
#define NST 32                  // 1024 / KC stages
// stage = {Ah, Al, Bh} each 128 rows x 64 B = 8 KB -> 24 KB
#define ST_BYTES 24576
#define DSMEM_BYTES (3 * ST_BYTES + 1024)

#define NPART 16                // kv partials per bh

// ---------------------------------------------------------------------------
// Scratch (device globals)
// ---------------------------------------------------------------------------
__device__ __align__(128) __half g_Qs [(size_t)M_ * K2];
__device__ __align__(128) __half g_VNs[(size_t)M_ * K2];
__device__ __align__(128) __half g_Wq [(size_t)D_ * K2];
__device__ __align__(128) __half g_Wk [(size_t)D_ * K2];
__device__ __align__(128) __half g_Wv [(size_t)D_ * K2];
__device__ __align__(128) __half g_Wo [(size_t)D_ * K2];
__device__ __align__(128) float g_phiq[(size_t)M_ * D_];
__device__ __align__(128) float g_phik[(size_t)M_ * D_];
__device__ __align__(128) float g_v   [(size_t)M_ * D_];
__device__ __align__(128) float g_KVp [64 * NPART * 64 * 64];
__device__ __align__(128) float g_Ksp [64 * NPART * 64];

// ---------------------------------------------------------------------------
// Helpers
// ---------------------------------------------------------------------------
__device__ __forceinline__ unsigned smem_u32(const void* p) {
    unsigned a;
    asm("{ .reg .u64 t; cvta.to.shared.u64 t, %1; cvt.u32.u64 %0, t; }"
        : "=r"(a) : "l"(p));
    return a;
}
// Swizzle for 64-byte rows (Swizzle<2,4,3>): bits[5:4] ^= bits[8:7]
#define SWZ64(o) ((o) ^ ((((unsigned)(o)) >> 3) & 0x30))

#define CP_ASYNC16(dst, src) \
    asm volatile("cp.async.cg.shared.global [%0], [%1], 16;" :: "r"(dst), "l"(src))
#define CP_COMMIT() asm volatile("cp.async.commit_group;" ::: "memory")
#define CP_WAIT1()  asm volatile("cp.async.wait_group 1;" ::: "memory")
#define CP_WAIT0()  asm volatile("cp.async.wait_group 0;" ::: "memory")

#define LDSM4(r, a) \
    asm volatile("ldmatrix.sync.aligned.m8n8.x4.shared.b16 {%0,%1,%2,%3}, [%4];" \
                 : "=r"((r)[0]), "=r"((r)[1]), "=r"((r)[2]), "=r"((r)[3]) : "r"(a))

#define MMA16816F(c, a, b0, b1) \
    asm volatile("mma.sync.aligned.m16n8k16.row.col.f32.f16.f16.f32 " \
                 "{%0,%1,%2,%3}, {%4,%5,%6,%7}, {%8,%9}, {%0,%1,%2,%3};" \
                 : "+f"((c)[0]), "+f"((c)[1]), "+f"((c)[2]), "+f"((c)[3]) \
                 : "r"((a)[0]), "r"((a)[1]), "r"((a)[2]), "r"((a)[3]),   \
                   "r"(b0), "r"(b1))

// ---------------------------------------------------------------------------
// Stage loader: {Ah, Al, Bh} for KC=32 columns; 6 cp.async per thread
// ---------------------------------------------------------------------------
__device__ __forceinline__ void load_stage(
    const __half* __restrict__ A, const __half* __restrict__ W,
    unsigned sb, int kb, int row0, int col0, int t)
{
    const int r = t >> 2, s = t & 3;        // r: 0..63, s: 16B segment
    const unsigned soff = s * 16;
#pragma unroll
    for (int i = 0; i < 2; i++) {
        const int rr = r + i * 64;
        const unsigned d = SWZ64(rr * 64 + soff);
        CP_ASYNC16(sb +         d, A + (size_t)(row0 + rr) * K2 + kb + s * 8);
        CP_ASYNC16(sb +  8192 + d, A + (size_t)(row0 + rr) * K2 + kb + 1024 + s * 8);
        CP_ASYNC16(sb + 16384 + d, W + (size_t)(col0 + rr) * K2 + kb + s * 8);
    }
}

// ---------------------------------------------------------------------------
// GEMM: C = Ah·Bh + Al·Bh (+bias, optional phi). fp16 2-term split.
// 256 threads = 8 warps (4 m x 2 n); warp computes 32x64. 32-stage, 3-ring.
// ---------------------------------------------------------------------------
__device__ __forceinline__ void tc_gemm_body(
    const __half* __restrict__ A, const __half* __restrict__ W,
    const float* __restrict__ bias, float* __restrict__ C, int act)
{
    extern __shared__ char dsm_raw[];
    unsigned draw = smem_u32(dsm_raw);
    unsigned sbase = (draw + 1023u) & ~1023u;

    const int t = threadIdx.x;
    const int wid = t >> 5, lane = t & 31;
    const int warp_m = wid & 3, warp_n = wid >> 2;
    const int row0 = blockIdx.y * BM;
    const int col0 = blockIdx.x * BN;

    float acc[2][8][4];
#pragma unroll
    for (int i = 0; i < 2; i++)
#pragma unroll
        for (int j = 0; j < 8; j++)
#pragma unroll
            for (int q = 0; q < 4; q++) acc[i][j][q] = 0.f;

    const int a_row = lane & 15, a_hi = (lane >> 4) * 16;
    const int b_g = lane >> 3;
    const int b_row = ((b_g >> 1) * 8) + (lane & 7);
    const int b_kb = (b_g & 1) * 16;

    load_stage(A, W, sbase,            0,  row0, col0, t); CP_COMMIT();
    load_stage(A, W, sbase + ST_BYTES, 32, row0, col0, t); CP_COMMIT();

    int stage = 0;
    for (int c = 0; c < NST; c++) {
        if (c == NST - 1) { CP_WAIT0(); } else { CP_WAIT1(); }
        __syncthreads();
        if (c + 2 < NST) {
            int ns = stage + 2; if (ns >= 3) ns -= 3;
            load_stage(A, W, sbase + ns * ST_BYTES, (c + 2) * KC, row0, col0, t);
            CP_COMMIT();
        }

        unsigned Ah = sbase + stage * ST_BYTES;
        unsigned Al = Ah + 8192;
        unsigned Bh = Ah + 16384;
#pragma unroll
        for (int ks = 0; ks < 2; ks++) {
            const unsigned a0off = SWZ64((warp_m * 32 + a_row) * 64 + ks * 32 + a_hi);
            const unsigned a1off = SWZ64((warp_m * 32 + 16 + a_row) * 64 + ks * 32 + a_hi);
            const unsigned b0off = SWZ64((warp_n * 64 + b_row) * 64 + ks * 32 + b_kb);
            const unsigned b1off = SWZ64((warp_n * 64 + 16 + b_row) * 64 + ks * 32 + b_kb);
            const unsigned b2off = SWZ64((warp_n * 64 + 32 + b_row) * 64 + ks * 32 + b_kb);
            const unsigned b3off = SWZ64((warp_n * 64 + 48 + b_row) * 64 + ks * 32 + b_kb);

            unsigned a[2][4], b[4][4];
            LDSM4(a[0], Ah + a0off);
            LDSM4(a[1], Ah + a1off);
            LDSM4(b[0], Bh + b0off);
            LDSM4(b[1], Bh + b1off);
            LDSM4(b[2], Bh + b2off);
            LDSM4(b[3], Bh + b3off);
            // Ah·Bh
#pragma unroll
            for (int mt = 0; mt < 2; mt++) {
                MMA16816F(acc[mt][0], a[mt], b[0][0], b[0][1]);
                MMA16816F(acc[mt][1], a[mt], b[0][2], b[0][3]);
                MMA16816F(acc[mt][2], a[mt], b[1][0], b[1][1]);
                MMA16816F(acc[mt][3], a[mt], b[1][2], b[1][3]);
                MMA16816F(acc[mt][4], a[mt], b[2][0], b[2][1]);
                MMA16816F(acc[mt][5], a[mt], b[2][2], b[2][3]);
                MMA16816F(acc[mt][6], a[mt], b[3][0], b[3][1]);
                MMA16816F(acc[mt][7], a[mt], b[3][2], b[3][3]);
            }
            // Al·Bh (reuse B fragments)
            {
                unsigned al[2][4];
                LDSM4(al[0], Al + a0off);
                LDSM4(al[1], Al + a1off);
#pragma unroll
                for (int mt = 0; mt < 2; mt++) {
                    MMA16816F(acc[mt][0], al[mt], b[0][0], b[0][1]);
                    MMA16816F(acc[mt][1], al[mt], b[0][2], b[0][3]);
                    MMA16816F(acc[mt][2], al[mt], b[1][0], b[1][1]);
                    MMA16816F(acc[mt][3], al[mt], b[1][2], b[1][3]);
                    MMA16816F(acc[mt][4], al[mt], b[2][0], b[2][1]);
                    MMA16816F(acc[mt][5], al[mt], b[2][2], b[2][3]);
                    MMA16816F(acc[mt][6], al[mt], b[3][0], b[3][1]);
                    MMA16816F(acc[mt][7], al[mt], b[3][2], b[3][3]);
                }
            }
        }
        stage++; if (stage >= 3) stage = 0;
    }

    // Epilogue
#pragma unroll
    for (int mt = 0; mt < 2; mt++) {
        int row = row0 + warp_m * 32 + mt * 16 + (lane >> 2);
#pragma unroll
        for (int nt = 0; nt < 8; nt++) {
            int col = col0 + warp_n * 64 + nt * 8 + (lane & 3) * 2;
            float bv0 = bias[col], bv1 = bias[col + 1];
            float o0 = acc[mt][nt][0] + bv0;
            float o1 = acc[mt][nt][1] + bv1;
            float o2 = acc[mt][nt][2] + bv0;
            float o3 = acc[mt][nt][3] + bv1;
            if (act) {
                o0 = o0 > 0.f ? o0 + 1.f : __expf(o0);
                o1 = o1 > 0.f ? o1 + 1.f : __expf(o1);
                o2 = o2 > 0.f ? o2 + 1.f : __expf(o2);
                o3 = o3 > 0.f ? o3 + 1.f : __expf(o3);
            }
            *(float2*)(C + (size_t)row * D_ + col)       = make_float2(o0, o1);
            *(float2*)(C + (size_t)(row + 8) * D_ + col) = make_float2(o2, o3);
        }
    }
}

__global__ __launch_bounds__(256, 2) void qkv_tc(
    const float* __restrict__ bQ, const float* __restrict__ bK,
    const float* __restrict__ bV)
{
    const int z = blockIdx.z;
    const __half* W  = (z == 0) ? g_Wq : (z == 1) ? g_Wk : g_Wv;
    const float* bb  = (z == 0) ? bQ   : (z == 1) ? bK   : bV;
    float* C         = (z == 0) ? g_phiq : (z == 1) ? g_phik : g_v;
    tc_gemm_body(g_Qs, W, bb, C, z < 2);
}

__global__ __launch_bounds__(256, 2) void out_tc(
    const float* __restrict__ bO, float* __restrict__ out)
{
    tc_gemm_body(g_VNs, g_Wo, bO, out, 0);
}

// ---------------------------------------------------------------------------
// fp32 -> fp16 2-term split, stored [hi | lo] with K2 row stride
// ---------------------------------------------------------------------------
__device__ __forceinline__ void split_one(
    const float* __restrict__ in, __half* __restrict__ out, size_t i)
{
    const float2 x = ((const float2*)in)[i];
    size_t r = i >> 9;
    int c2 = (int)(i & 511);
    __half h0 = __float2half_rn(x.x), h1 = __float2half_rn(x.y);
    __half l0 = __float2half_rn(x.x - __half2float(h0));
    __half l1 = __float2half_rn(x.y - __half2float(h1));
    unsigned hv = ((unsigned)__half_as_ushort(h1) << 16) | __half_as_ushort(h0);
    unsigned lv = ((unsigned)__half_as_ushort(l1) << 16) | __half_as_ushort(l0);
    unsigned* o = (unsigned*)(out + r * K2) + c2;
    o[0] = hv; o[512] = lv;
}

__global__ __launch_bounds__(256) void split_q_kernel(const float* __restrict__ Q)
{
    split_one(Q, g_Qs, (size_t)blockIdx.x * 256 + threadIdx.x);
}

__global__ __launch_bounds__(256) void split_w_kernel(
    const float* __restrict__ WQ, const float* __restrict__ WK,
    const float* __restrict__ WV, const float* __restrict__ WO)
{
    const int z = blockIdx.y;
    const float* in = (z == 0) ? WQ : (z == 1) ? WK : (z == 2) ? WV : WO;
    __half* out = (z == 0) ? g_Wq : (z == 1) ? g_Wk : (z == 2) ? g_Wv : g_Wo;
    split_one(in, out, (size_t)blockIdx.x * 256 + threadIdx.x);
}

// ---------------------------------------------------------------------------
// KV partial accumulation: block (bh, y) handles 256 l-rows (no atomics)
// ---------------------------------------------------------------------------
__global__ __launch_bounds__(256) void kv_kernel()
{
    const int bh = blockIdx.x;
    const int b = bh >> 4, h = bh & 15;
    const int l0 = blockIdx.y * 256;

    __shared__ float ks[16][64];
    __shared__ float vs[16][64];

    const int t = threadIdx.x;
    const int td = t >> 4, tmm = t & 15;
    const int lr = t >> 4, lc = (t & 15) * 4;

    float acc[4][4];
    float ksum[4] = {0.f, 0.f, 0.f, 0.f};
#pragma unroll
    for (int i = 0; i < 4; i++)
#pragma unroll
        for (int j = 0; j < 4; j++) acc[i][j] = 0.f;

    for (int lt = 0; lt < 256; lt += 16) {
        size_t base = ((size_t)(b * L_ + l0 + lt + lr)) * D_ + h * 64 + lc;
        float4 kq = *(const float4*)(g_phik + base);
        float4 vq = *(const float4*)(g_v + base);
        __syncthreads();
        *(float4*)&ks[lr][lc] = kq;
        *(float4*)&vs[lr][lc] = vq;
        __syncthreads();
#pragma unroll
        for (int ll = 0; ll < 16; ll++) {
            float ka[4], va[4];
#pragma unroll
            for (int i = 0; i < 4; i++) ka[i] = ks[ll][td * 4 + i];
#pragma unroll
            for (int j = 0; j < 4; j++) va[j] = vs[ll][tmm * 4 + j];
#pragma unroll
            for (int i = 0; i < 4; i++)
#pragma unroll
                for (int j = 0; j < 4; j++) acc[i][j] += ka[i] * va[j];
            if (tmm == 0) {
#pragma unroll
                for (int i = 0; i < 4; i++) ksum[i] += ka[i];
            }
        }
    }

    float* kvout = g_KVp + ((size_t)bh * NPART + blockIdx.y) * 4096;
#pragma unroll
    for (int i = 0; i < 4; i++)
#pragma unroll
        for (int j = 0; j < 4; j++)
            kvout[(td * 4 + i) * 64 + tmm * 4 + j] = acc[i][j];
    if (tmm == 0) {
#pragma unroll
        for (int i = 0; i < 4; i++)
            g_Ksp[((size_t)bh * NPART + blockIdx.y) * 64 + td * 4 + i] = ksum[i];
    }
}

// ---------------------------------------------------------------------------
// V_new: sums KV partials, warp handles 4 rows/pass, vectorized d-loop.
// Writes fp16 split [hi|lo] into g_VNs (K2 stride). Block covers 256 l-rows.
// ---------------------------------------------------------------------------
__global__ __launch_bounds__(256) void vnew_kernel()
{
    const int bh = blockIdx.x;
    const int b = bh >> 4, h = bh & 15;
    const int l0 = blockIdx.y * 256;

    __shared__ float KVs[64][64];
    __shared__ float Ks[64];
    __shared__ float pqs[8][4][64];

    const int t = threadIdx.x, w = t >> 5, lane = t & 31;

    for (int i = t; i < 1024; i += 256) {
        float4 s = make_float4(0.f, 0.f, 0.f, 0.f);
#pragma unroll
        for (int p = 0; p < NPART; p++) {
            float4 v = ((const float4*)(g_KVp + ((size_t)bh * NPART + p) * 4096))[i];
            s.x += v.x; s.y += v.y; s.z += v.z; s.w += v.w;
        }
        ((float4*)KVs)[i] = s;
    }
    if (t < 64) {
        float s = 0.f;
#pragma unroll
        for (int p = 0; p < NPART; p++) s += g_Ksp[((size_t)bh * NPART + p) * 64 + t];
        Ks[t] = s;
    }
    __syncthreads();

    const int prow = lane >> 3;          // 0..3
    const int pcol = (lane & 7) * 8;     // 0..56

    for (int s = 0; s < 8; s++) {
        const int lb = l0 + s * 32 + w * 4;
        const float* pq = g_phiq + ((size_t)(b * L_ + lb + prow)) * D_ + h * 64 + pcol;
        float4 pa = *(const float4*)pq;
        float4 pb = *(const float4*)(pq + 4);
        *(float4*)&pqs[w][prow][pcol]     = pa;
        *(float4*)&pqs[w][prow][pcol + 4] = pb;

        float zp = pa.x * Ks[pcol]     + pa.y * Ks[pcol + 1]
                 + pa.z * Ks[pcol + 2] + pa.w * Ks[pcol + 3]
                 + pb.x * Ks[pcol + 4] + pb.y * Ks[pcol + 5]
                 + pb.z * Ks[pcol + 6] + pb.w * Ks[pcol + 7];
        zp += __shfl_xor_sync(0xffffffffu, zp, 1);
        zp += __shfl_xor_sync(0xffffffffu, zp, 2);
        zp += __shfl_xor_sync(0xffffffffu, zp, 4);
        float z0 = 1.f / (__shfl_sync(0xffffffffu, zp, 0)  + EPS_);
        float z1 = 1.f / (__shfl_sync(0xffffffffu, zp, 8)  + EPS_);
        float z2 = 1.f / (__shfl_sync(0xffffffffu, zp, 16) + EPS_);
        float z3 = 1.f / (__shfl_sync(0xffffffffu, zp, 24) + EPS_);
        __syncwarp();

        float2 a0 = {0.f, 0.f}, a1 = {0.f, 0.f}, a2 = {0.f, 0.f}, a3 = {0.f, 0.f};
        const float4* q40 = (const float4*)&pqs[w][0][0];
        const float4* q41 = (const float4*)&pqs[w][1][0];
        const float4* q42 = (const float4*)&pqs[w][2][0];
        const float4* q43 = (const float4*)&pqs[w][3][0];
#pragma unroll
        for (int d4 = 0; d4 < 16; d4++) {
            float4 q0 = q40[d4], q1 = q41[d4], q2 = q42[d4], q3 = q43[d4];
            float2 kv0 = *(const float2*)&KVs[d4 * 4 + 0][lane * 2];
            float2 kv1 = *(const float2*)&KVs[d4 * 4 + 1][lane * 2];
            float2 kv2 = *(const float2*)&KVs[d4 * 4 + 2][lane * 2];
            float2 kv3 = *(const float2*)&KVs[d4 * 4 + 3][lane * 2];
            a0.x += q0.x * kv0.x + q0.y * kv1.x + q0.z * kv2.x + q0.w * kv3.x;
            a0.y += q0.x * kv0.y + q0.y * kv1.y + q0.z * kv2.y + q0.w * kv3.y;
            a1.x += q1.x * kv0.x + q1.y * kv1.x + q1.z * kv2.x + q1.w * kv3.x;
            a1.y += q1.x * kv0.y + q1.y * kv1.y + q1.z * kv2.y + q1.w * kv3.y;
            a2.x += q2.x * kv0.x + q2.y * kv1.x + q2.z * kv2.x + q2.w * kv3.x;
            a2.y += q2.x * kv0.y + q2.y * kv1.y + q2.z * kv2.y + q2.w * kv3.y;
            a3.x += q3.x * kv0.x + q3.y * kv1.x + q3.z * kv2.x + q3.w * kv3.x;
            a3.y += q3.x * kv0.y + q3.y * kv1.y + q3.z * kv2.y + q3.w * kv3.y;
        }

        float2 vv[4] = {
            {a0.x * z0, a0.y * z0}, {a1.x * z1, a1.y * z1},
            {a2.x * z2, a2.y * z2}, {a3.x * z3, a3.y * z3}
        };
#pragma unroll
        for (int j = 0; j < 4; j++) {
            __half h0 = __float2half_rn(vv[j].x);
            __half h1 = __float2half_rn(vv[j].y);
            __half q0 = __float2half_rn(vv[j].x - __half2float(h0));
            __half q1 = __float2half_rn(vv[j].y - __half2float(h1));
            unsigned hv = ((unsigned)__half_as_ushort(h1) << 16) | __half_as_ushort(h0);
            unsigned lv = ((unsigned)__half_as_ushort(q1) << 16) | __half_as_ushort(q0);
            unsigned* p = (unsigned*)(g_VNs + (size_t)(b * L_ + lb + j) * K2) + h * 32 + lane;
            p[0] = hv; p[512] = lv;
        }
        __syncwarp();
    }
}

// ---------------------------------------------------------------------------
// Launch
// ---------------------------------------------------------------------------
extern "C" void kernel_launch(void* const* d_in, const int* in_sizes, int n_in,
                              void* d_out, int out_size)
{
    const float* Q  = (const float*)d_in[0];
    const float* WQ = (const float*)d_in[1];
    const float* bQ = (const float*)d_in[2];
    const float* WK = (const float*)d_in[3];
    const float* bK = (const float*)d_in[4];
    const float* WV = (const float*)d_in[5];
    const float* bV = (const float*)d_in[6];
    const float* WO = (const float*)d_in[7];
    const float* bO = (const float*)d_in[8];
    float* out = (float*)d_out;

    cudaFuncSetAttribute(qkv_tc, cudaFuncAttributeMaxDynamicSharedMemorySize, DSMEM_BYTES);
    cudaFuncSetAttribute(out_tc, cudaFuncAttributeMaxDynamicSharedMemorySize, DSMEM_BYTES);

    split_q_kernel<<<(M_ * 512) / 256, 256>>>(Q);
    {
        dim3 grid((D_ * 512) / 256, 4);
        split_w_kernel<<<grid, 256>>>(WQ, WK, WV, WO);
    }

    {
        dim3 grid(D_ / BN, M_ / BM, 3);
        qkv_tc<<<grid, 256, DSMEM_BYTES>>>(bQ, bK, bV);
    }
    {
        dim3 grid(64, NPART);
        kv_kernel<<<grid, 256>>>();
    }
    {
        dim3 grid(64, NPART);
        vnew_kernel<<<grid, 256>>>();
    }
    {
        dim3 grid(D_ / BN, M_ / BM);
        out_tc<<<grid, 256, DSMEM_BYTES>>>(bO, out);
    }
}